// round 3
// baseline (speedup 1.0000x reference)
#include <cuda_runtime.h>
#include <cstddef>

#define S_LEN 4096
#define HID   4096
#define NQ    32
#define NKV   8
#define HD    128
#define HALF  64
#define GRP   4
#define QKV_N (NQ*HD + 2*NKV*HD)   /* 6144 */
#define ATT_SCALE 0.08838834764831845f /* 128^-0.5 */

/* ---------------- scratch (device globals: allocation-free) -------------- */
__device__ float g_qkv [(size_t)S_LEN * QKV_N];        /* 96 MB  */
__device__ float g_q   [(size_t)NQ  * S_LEN * HD];     /* 64 MB  [head][s][d] */
__device__ float g_k   [(size_t)NKV * S_LEN * HD];     /* 16 MB  */
__device__ float g_v   [(size_t)NKV * S_LEN * HD];     /* 16 MB  */
__device__ float g_attn[(size_t)S_LEN * NQ * HD];      /* 64 MB  [s][h*D+d] */

/* ---------------- generic 128x128x8 register-tiled SGEMM ----------------- */
/* A: MxK row-major, B: KxN row-major, C: MxN row-major. M,N %128==0, K%8==0 */
__global__ __launch_bounds__(256) void sgemm128(const float* __restrict__ A,
                                                const float* __restrict__ B,
                                                float* __restrict__ C,
                                                int M, int N, int K) {
    __shared__ float As[8 * 128];   /* transposed: As[k][m] */
    __shared__ float Bs[8 * 128];   /* Bs[k][n] */
    const int tid = threadIdx.x;
    const int tx  = tid & 15;
    const int ty  = tid >> 4;
    const int m0  = blockIdx.y * 128;
    const int n0  = blockIdx.x * 128;

    const int a_r = tid >> 1;            /* 0..127 */
    const int a_c = (tid & 1) * 4;       /* 0 or 4 */
    const int b_r = tid >> 5;            /* 0..7   */
    const int b_c = (tid & 31) * 4;      /* 0..124 */

    const float* Aptr = A + (size_t)(m0 + a_r) * K + a_c;
    const float* Bptr = B + (size_t)b_r * N + n0 + b_c;

    float acc[8][8];
#pragma unroll
    for (int i = 0; i < 8; i++)
#pragma unroll
        for (int j = 0; j < 8; j++) acc[i][j] = 0.0f;

    for (int k0 = 0; k0 < K; k0 += 8) {
        float4 av = *(const float4*)(Aptr + k0);
        float4 bv = *(const float4*)(Bptr + (size_t)k0 * N);
        As[(a_c + 0) * 128 + a_r] = av.x;
        As[(a_c + 1) * 128 + a_r] = av.y;
        As[(a_c + 2) * 128 + a_r] = av.z;
        As[(a_c + 3) * 128 + a_r] = av.w;
        *(float4*)(Bs + b_r * 128 + b_c) = bv;
        __syncthreads();
#pragma unroll
        for (int kk = 0; kk < 8; kk++) {
            float ra[8], rb[8];
#pragma unroll
            for (int i = 0; i < 8; i++) ra[i] = As[kk * 128 + ty + 16 * i]; /* broadcast */
#pragma unroll
            for (int j = 0; j < 8; j++) rb[j] = Bs[kk * 128 + tx + 16 * j]; /* conflict-free */
#pragma unroll
            for (int i = 0; i < 8; i++)
#pragma unroll
                for (int j = 0; j < 8; j++) acc[i][j] += ra[i] * rb[j];
        }
        __syncthreads();
    }
#pragma unroll
    for (int i = 0; i < 8; i++)
#pragma unroll
        for (int j = 0; j < 8; j++)
            C[(size_t)(m0 + ty + 16 * i) * N + n0 + tx + 16 * j] = acc[i][j];
}

/* ---------------- RoPE + split/rearrange to per-head layouts ------------- */
__global__ __launch_bounds__(256) void rope_split(const int* __restrict__ positions) {
    const int s = blockIdx.x;
    const float* row = g_qkv + (size_t)s * QKV_N;
    const float pos = (float)positions[s];
    const int tid = threadIdx.x;
    const float LN_THETA_OVER_HALF = 9.210340371976184f / 64.0f; /* ln(10000)/64 */

    /* Q heads: rope */
    for (int idx = tid; idx < NQ * HALF; idx += 256) {
        int h = idx >> 6, j = idx & 63;
        float inv = expf(-(float)j * LN_THETA_OVER_HALF);
        float f = pos * inv;
        float c = cosf(f), sn = sinf(f);
        float x1 = row[h * HD + j];
        float x2 = row[h * HD + HALF + j];
        float* o = g_q + ((size_t)h * S_LEN + s) * HD;
        o[j]        = x1 * c - x2 * sn;
        o[HALF + j] = x2 * c + x1 * sn;
    }
    /* K heads: rope */
    for (int idx = tid; idx < NKV * HALF; idx += 256) {
        int h = idx >> 6, j = idx & 63;
        float inv = expf(-(float)j * LN_THETA_OVER_HALF);
        float f = pos * inv;
        float c = cosf(f), sn = sinf(f);
        const float* kr = row + NQ * HD;
        float x1 = kr[h * HD + j];
        float x2 = kr[h * HD + HALF + j];
        float* o = g_k + ((size_t)h * S_LEN + s) * HD;
        o[j]        = x1 * c - x2 * sn;
        o[HALF + j] = x2 * c + x1 * sn;
    }
    /* V: copy */
    for (int idx = tid; idx < NKV * HD; idx += 256) {
        int h = idx >> 7, d = idx & 127;
        g_v[((size_t)h * S_LEN + s) * HD + d] = row[NQ * HD + NKV * HD + h * HD + d];
    }
}

/* ---------------- flash attention: Br=64, Bc=64, causal ------------------ */
/* grid = (S/64, NQ); 256 threads; dynamic smem = 115200 B                   */
__global__ __launch_bounds__(256) void attn_kernel(const int* __restrict__ positions) {
    extern __shared__ float sm[];
    float* Qs = sm;                 /* 64 x 128 (pitch 128, broadcast reads)  */
    float* Ks = Qs + 64 * 128;      /* 64 x pitch 129 (kills row conflicts)   */
    float* Vs = Ks + 64 * 129;      /* 64 x 128 (broadcast/consecutive reads) */
    float* Ps = Vs + 64 * 128;      /* 64 x pitch 65                          */

    const int h  = blockIdx.y;
    const int qt = blockIdx.x;
    const int g  = h / GRP;
    const int tid = threadIdx.x;
    const int tx  = tid & 15;
    const int ty  = tid >> 4;
    const int r0  = ty * 4;

    /* load Q tile */
    const float* qbase = g_q + ((size_t)h * S_LEN + (size_t)qt * 64) * HD;
    for (int i = tid; i < 64 * 128 / 4; i += 256)
        ((float4*)Qs)[i] = ((const float4*)qbase)[i];

    float m_i[4], l_i[4], acc[4][8];
#pragma unroll
    for (int i = 0; i < 4; i++) {
        m_i[i] = -1e30f; l_i[i] = 0.0f;
#pragma unroll
        for (int j = 0; j < 8; j++) acc[i][j] = 0.0f;
    }
    int qpos[4];
#pragma unroll
    for (int i = 0; i < 4; i++) qpos[i] = positions[qt * 64 + r0 + i];

    for (int kt = 0; kt <= qt; kt++) {
        __syncthreads();  /* protect Ks/Vs/Ps from previous iter readers; first iter: Q ready */
        const float* kbase = g_k + ((size_t)g * S_LEN + (size_t)kt * 64) * HD;
        const float* vbase = g_v + ((size_t)g * S_LEN + (size_t)kt * 64) * HD;
        for (int idx = tid; idx < 64 * 128; idx += 256) {
            int r = idx >> 7, d = idx & 127;
            Ks[r * 129 + d] = kbase[idx];
        }
        for (int i = tid; i < 64 * 128 / 4; i += 256)
            ((float4*)Vs)[i] = ((const float4*)vbase)[i];
        __syncthreads();

        /* S = Q K^T  (4x4 per thread; cols tx+16j) */
        float sc[4][4];
#pragma unroll
        for (int i = 0; i < 4; i++)
#pragma unroll
            for (int j = 0; j < 4; j++) sc[i][j] = 0.0f;
#pragma unroll 4
        for (int d = 0; d < 128; d++) {
            float qv[4], kv[4];
#pragma unroll
            for (int i = 0; i < 4; i++) qv[i] = Qs[(r0 + i) * 128 + d];
#pragma unroll
            for (int j = 0; j < 4; j++) kv[j] = Ks[(tx + 16 * j) * 129 + d];
#pragma unroll
            for (int i = 0; i < 4; i++)
#pragma unroll
                for (int j = 0; j < 4; j++) sc[i][j] += qv[i] * kv[j];
        }

        int kpos[4];
#pragma unroll
        for (int j = 0; j < 4; j++) kpos[j] = positions[kt * 64 + tx + 16 * j];
#pragma unroll
        for (int i = 0; i < 4; i++)
#pragma unroll
            for (int j = 0; j < 4; j++) {
                float v = sc[i][j] * ATT_SCALE;
                sc[i][j] = (qpos[i] >= kpos[j]) ? v : -1e30f;
            }

        /* online softmax stats (reduce across the 16 tx lanes) */
        float mt[4];
#pragma unroll
        for (int i = 0; i < 4; i++)
            mt[i] = fmaxf(fmaxf(sc[i][0], sc[i][1]), fmaxf(sc[i][2], sc[i][3]));
#pragma unroll
        for (int off = 8; off >= 1; off >>= 1)
#pragma unroll
            for (int i = 0; i < 4; i++)
                mt[i] = fmaxf(mt[i], __shfl_xor_sync(0xffffffffu, mt[i], off));

        float alpha[4], rs[4];
#pragma unroll
        for (int i = 0; i < 4; i++) {
            float mnew = fmaxf(m_i[i], mt[i]);
            alpha[i] = __expf(m_i[i] - mnew);
            m_i[i] = mnew;
            float s4 = 0.0f;
#pragma unroll
            for (int j = 0; j < 4; j++) {
                float p = __expf(sc[i][j] - mnew);
                sc[i][j] = p;
                s4 += p;
            }
            rs[i] = s4;
        }
#pragma unroll
        for (int off = 8; off >= 1; off >>= 1)
#pragma unroll
            for (int i = 0; i < 4; i++)
                rs[i] += __shfl_xor_sync(0xffffffffu, rs[i], off);
#pragma unroll
        for (int i = 0; i < 4; i++) {
            l_i[i] = l_i[i] * alpha[i] + rs[i];
#pragma unroll
            for (int jj = 0; jj < 8; jj++) acc[i][jj] *= alpha[i];
        }

        /* stash P, then acc += P V */
#pragma unroll
        for (int i = 0; i < 4; i++)
#pragma unroll
            for (int j = 0; j < 4; j++)
                Ps[(r0 + i) * 65 + tx + 16 * j] = sc[i][j];
        __syncthreads();

#pragma unroll 4
        for (int c = 0; c < 64; c++) {
            float pv[4], vv[8];
#pragma unroll
            for (int i = 0; i < 4; i++) pv[i] = Ps[(r0 + i) * 65 + c]; /* broadcast */
#pragma unroll
            for (int jj = 0; jj < 8; jj++) vv[jj] = Vs[c * 128 + tx + 16 * jj];
#pragma unroll
            for (int i = 0; i < 4; i++)
#pragma unroll
                for (int jj = 0; jj < 8; jj++) acc[i][jj] += pv[i] * vv[jj];
        }
    }

    /* normalize + write [s][h*D + d] */
#pragma unroll
    for (int i = 0; i < 4; i++) {
        float inv = 1.0f / l_i[i];
#pragma unroll
        for (int jj = 0; jj < 8; jj++)
            g_attn[(size_t)(qt * 64 + r0 + i) * (NQ * HD) + h * HD + tx + 16 * jj] =
                acc[i][jj] * inv;
    }
}

/* ------------------------------- launch ---------------------------------- */
extern "C" void kernel_launch(void* const* d_in, const int* in_sizes, int n_in,
                              void* d_out, int out_size) {
    const int*   positions = (const int*)  d_in[0];
    const float* hidden    = (const float*)d_in[1];
    const float* w_qkv     = (const float*)d_in[2];
    const float* w_o       = (const float*)d_in[3];
    float*       out       = (float*)d_out;
    (void)in_sizes; (void)n_in; (void)out_size;

    void *p_qkv = nullptr, *p_attn = nullptr;
    cudaGetSymbolAddress(&p_qkv,  g_qkv);
    cudaGetSymbolAddress(&p_attn, g_attn);

    /* 1) QKV projection: [S,H] @ [H,6144] */
    sgemm128<<<dim3(QKV_N / 128, S_LEN / 128), 256>>>(hidden, w_qkv,
                                                      (float*)p_qkv,
                                                      S_LEN, QKV_N, HID);
    /* 2) RoPE + split into per-head Q/K/V */
    rope_split<<<S_LEN, 256>>>(positions);

    /* 3) causal flash attention */
    const int smem_bytes = (64 * 128 + 64 * 129 + 64 * 128 + 64 * 65) * 4; /* 115200 */
    cudaFuncSetAttribute(attn_kernel, cudaFuncAttributeMaxDynamicSharedMemorySize,
                         smem_bytes);
    attn_kernel<<<dim3(S_LEN / 64, NQ), 256, smem_bytes>>>(positions);

    /* 4) output projection: [S,4096] @ [4096,4096] */
    sgemm128<<<dim3(HID / 128, S_LEN / 128), 256>>>((const float*)p_attn, w_o,
                                                    out, S_LEN, HID, HID);
}

// round 7
// speedup vs baseline: 1.5696x; 1.5696x over previous
#include <cuda_runtime.h>
#include <cuda_bf16.h>
#include <cstdint>
#include <cstddef>

#define S_LEN 4096
#define HID   4096
#define NQ    32
#define NKV   8
#define HD    128
#define HALF  64
#define GRP   4
#define QKV_N (NQ*HD + 2*NKV*HD)   /* 6144 */
#define ATT_SCALE 0.08838834764831845f
#define KP    (3*HID)              /* 12288 split-bf16 K */
#define KTILE 64
#define KITER (KP/KTILE)           /* 192 */

/* ---------------- scratch (device globals: allocation-free) -------------- */
__device__ float g_qkv [(size_t)S_LEN * QKV_N];
__device__ float g_q   [(size_t)NQ  * S_LEN * HD];
__device__ float g_k   [(size_t)NKV * S_LEN * HD];
__device__ float g_v   [(size_t)NKV * S_LEN * HD];
__device__ float g_attn[(size_t)S_LEN * NQ * HD];
__device__ __nv_bfloat16 g_Abf [(size_t)S_LEN * KP];   /* split activations  */
__device__ __nv_bfloat16 g_Wq  [(size_t)QKV_N * KP];   /* split w_qkv^T      */
__device__ __nv_bfloat16 g_Wo  [(size_t)HID   * KP];   /* split w_o^T        */

/* ======================= small asm helpers =============================== */
__device__ __forceinline__ uint32_t smem_u32(const void* p) {
    uint32_t a;
    asm("{ .reg .u64 t; cvta.to.shared.u64 t, %1; cvt.u32.u64 %0, t; }"
        : "=r"(a) : "l"(p));
    return a;
}
__device__ __forceinline__ uint32_t sw128(uint32_t off) {   /* Swizzle<3,4,3> */
    return off ^ ((off >> 3) & 0x70);
}
__device__ __forceinline__ void cp_async16(uint32_t saddr, const void* gaddr) {
    asm volatile("cp.async.cg.shared.global [%0], [%1], 16;"
                 :: "r"(saddr), "l"(gaddr));
}
#define CP_COMMIT() asm volatile("cp.async.commit_group;" ::: "memory")
#define CP_WAIT(n)  asm volatile("cp.async.wait_group %0;" :: "n"(n) : "memory")

__device__ __forceinline__ void ldsm_x4(uint32_t* f, uint32_t addr) {
    asm volatile("ldmatrix.sync.aligned.m8n8.x4.shared.b16 {%0,%1,%2,%3}, [%4];"
                 : "=r"(f[0]), "=r"(f[1]), "=r"(f[2]), "=r"(f[3]) : "r"(addr));
}
__device__ __forceinline__ void mma16816(float* d, const uint32_t* a,
                                         uint32_t b0, uint32_t b1) {
    asm volatile("mma.sync.aligned.m16n8k16.row.col.f32.bf16.bf16.f32 "
                 "{%0,%1,%2,%3}, {%4,%5,%6,%7}, {%8,%9}, {%0,%1,%2,%3};"
                 : "+f"(d[0]), "+f"(d[1]), "+f"(d[2]), "+f"(d[3])
                 : "r"(a[0]), "r"(a[1]), "r"(a[2]), "r"(a[3]), "r"(b0), "r"(b1));
}

/* ================= split-bf16 conversion kernels ========================= */
/* rows x 4096 fp32 -> rows x 12288 bf16: segs [hi | hi | lo]                */
__global__ __launch_bounds__(256) void split_rows(const float* __restrict__ src,
                                                  __nv_bfloat16* __restrict__ dst) {
    size_t idx = (size_t)blockIdx.x * 256 + threadIdx.x;
    int r = (int)(idx >> 12), k = (int)(idx & 4095);
    float x = src[idx];
    __nv_bfloat16 hi = __float2bfloat16_rn(x);
    __nv_bfloat16 lo = __float2bfloat16_rn(x - __bfloat162float(hi));
    size_t base = (size_t)r * KP + k;
    dst[base]          = hi;
    dst[base + HID]    = hi;
    dst[base + 2*HID]  = lo;
}
/* W[4096, N] fp32 -> Wt[N, 12288] bf16: segs [hi | lo | hi] (transpose)      */
__global__ __launch_bounds__(256) void split_wt(const float* __restrict__ src,
                                                __nv_bfloat16* __restrict__ dst, int N) {
    __shared__ float t[32][33];
    int kb = blockIdx.x * 32, nb = blockIdx.y * 32;
    int tx = threadIdx.x, ty = threadIdx.y;
#pragma unroll
    for (int i = 0; i < 32; i += 8)
        t[ty + i][tx] = src[(size_t)(kb + ty + i) * N + nb + tx];
    __syncthreads();
#pragma unroll
    for (int i = 0; i < 32; i += 8) {
        int n = nb + ty + i, k = kb + tx;
        float x = t[tx][ty + i];
        __nv_bfloat16 hi = __float2bfloat16_rn(x);
        __nv_bfloat16 lo = __float2bfloat16_rn(x - __bfloat162float(hi));
        size_t base = (size_t)n * KP + k;
        dst[base]         = hi;
        dst[base + HID]   = lo;
        dst[base + 2*HID] = hi;
    }
}

/* ========== mma.sync bf16 GEMM: C[M,N] = A[M,KP] x B^T (B:[N,KP]) ========= */
/* CTA tile 128x128, K-tile 64; 8 warps in 2(m) x 4(n); warp tile 64x32.      */
/* SMEM per stage: A 16KB + B 16KB; 2 stages = 64KB. cp.async double buffer.  */
#define TILE_BYTES 16384

__global__ __launch_bounds__(256) void gemm_mma(const __nv_bfloat16* __restrict__ A,
                                                const __nv_bfloat16* __restrict__ B,
                                                float* __restrict__ C, int N) {
    extern __shared__ char smc[];
    const uint32_t smb = smem_u32(smc);
    const int tid  = threadIdx.x;
    const int lane = tid & 31;
    const int wid  = tid >> 5;
    const int wm   = wid & 1;          /* 0..1 */
    const int wn   = wid >> 1;         /* 0..3 */
    const int m0   = blockIdx.x * 128;
    const int n0   = blockIdx.y * 128;

    const uint32_t sA[2] = { smb,              smb + 2*TILE_BYTES };
    const uint32_t sB[2] = { smb + TILE_BYTES, smb + 3*TILE_BYTES };

    /* loader mapping: thread t -> row r = t>>1, chunk half = t&1 (4x16B)     */
    const int r    = tid >> 1;
    const int halfc= tid & 1;
    const __nv_bfloat16* gA = A + (size_t)(m0 + r) * KP + halfc * 32;
    const __nv_bfloat16* gB = B + (size_t)(n0 + r) * KP + halfc * 32;
    const uint32_t soff[4] = {
        sw128((uint32_t)r * 128u + (uint32_t)(halfc * 4 + 0) * 16u),
        sw128((uint32_t)r * 128u + (uint32_t)(halfc * 4 + 1) * 16u),
        sw128((uint32_t)r * 128u + (uint32_t)(halfc * 4 + 2) * 16u),
        sw128((uint32_t)r * 128u + (uint32_t)(halfc * 4 + 3) * 16u) };

    float acc[4][4][4];
#pragma unroll
    for (int i = 0; i < 4; i++)
#pragma unroll
        for (int j = 0; j < 4; j++)
#pragma unroll
            for (int q = 0; q < 4; q++) acc[i][j][q] = 0.0f;

    /* ldmatrix row/chunk mapping */
    const int arow = wm * 64 + (lane & 15);
    const int brow = wn * 32 + (lane & 15);
    const int kc   = lane >> 4;                 /* 0/1: 16B k-chunk           */

    /* prologue: 2 stages in flight */
#pragma unroll
    for (int p = 0; p < 2; p++) {
        const __nv_bfloat16* pa = gA + (size_t)p * KTILE;
        const __nv_bfloat16* pb = gB + (size_t)p * KTILE;
#pragma unroll
        for (int j = 0; j < 4; j++) {
            cp_async16(sA[p] + soff[j], pa + j * 8);
            cp_async16(sB[p] + soff[j], pb + j * 8);
        }
        CP_COMMIT();
    }

    for (int it = 0; it < KITER; ++it) {
        const int s = it & 1;
        if (it + 1 < KITER) CP_WAIT(1); else CP_WAIT(0);
        __syncthreads();

#pragma unroll
        for (int ks = 0; ks < 4; ks++) {
            uint32_t aF[4][4], bF[2][4];
            const uint32_t acol = (uint32_t)(ks * 2 + kc) * 16u;
#pragma unroll
            for (int mt = 0; mt < 4; mt++)
                ldsm_x4(aF[mt], sA[s] + sw128((uint32_t)(arow + mt * 16) * 128u + acol));
            ldsm_x4(bF[0], sB[s] + sw128((uint32_t)(brow)      * 128u + acol));
            ldsm_x4(bF[1], sB[s] + sw128((uint32_t)(brow + 16) * 128u + acol));
#pragma unroll
            for (int mt = 0; mt < 4; mt++)
#pragma unroll
                for (int nt = 0; nt < 4; nt++) {
                    const int gsel = nt >> 1, sub = nt & 1;
                    mma16816(acc[mt][nt], aF[mt], bF[gsel][sub], bF[gsel][sub + 2]);
                }
        }
        __syncthreads();

        if (it + 2 < KITER) {
            const int sn = s;   /* stage just freed */
            const __nv_bfloat16* pa = gA + (size_t)(it + 2) * KTILE;
            const __nv_bfloat16* pb = gB + (size_t)(it + 2) * KTILE;
#pragma unroll
            for (int j = 0; j < 4; j++) {
                cp_async16(sA[sn] + soff[j], pa + j * 8);
                cp_async16(sB[sn] + soff[j], pb + j * 8);
            }
            CP_COMMIT();
        }
    }

    /* epilogue: direct fp32 stores (float2 per fragment row)               */
#pragma unroll
    for (int mt = 0; mt < 4; mt++) {
        const int row0 = m0 + wm * 64 + mt * 16 + (lane >> 2);
#pragma unroll
        for (int nt = 0; nt < 4; nt++) {
            const int col = n0 + wn * 32 + nt * 8 + (lane & 3) * 2;
            float2 lo = { acc[mt][nt][0], acc[mt][nt][1] };
            float2 hi = { acc[mt][nt][2], acc[mt][nt][3] };
            *(float2*)(C + (size_t)row0 * N + col)       = lo;
            *(float2*)(C + (size_t)(row0 + 8) * N + col) = hi;
        }
    }
}

/* ---------------- RoPE + split/rearrange to per-head layouts ------------- */
__global__ __launch_bounds__(256) void rope_split(const int* __restrict__ positions) {
    const int s = blockIdx.x;
    const float* row = g_qkv + (size_t)s * QKV_N;
    const float pos = (float)positions[s];
    const int tid = threadIdx.x;
    const float LN_THETA_OVER_HALF = 9.210340371976184f / 64.0f;

    for (int idx = tid; idx < NQ * HALF; idx += 256) {
        int h = idx >> 6, j = idx & 63;
        float inv = expf(-(float)j * LN_THETA_OVER_HALF);
        float f = pos * inv;
        float c = cosf(f), sn = sinf(f);
        float x1 = row[h * HD + j];
        float x2 = row[h * HD + HALF + j];
        float* o = g_q + ((size_t)h * S_LEN + s) * HD;
        o[j]        = x1 * c - x2 * sn;
        o[HALF + j] = x2 * c + x1 * sn;
    }
    for (int idx = tid; idx < NKV * HALF; idx += 256) {
        int h = idx >> 6, j = idx & 63;
        float inv = expf(-(float)j * LN_THETA_OVER_HALF);
        float f = pos * inv;
        float c = cosf(f), sn = sinf(f);
        const float* kr = row + NQ * HD;
        float x1 = kr[h * HD + j];
        float x2 = kr[h * HD + HALF + j];
        float* o = g_k + ((size_t)h * S_LEN + s) * HD;
        o[j]        = x1 * c - x2 * sn;
        o[HALF + j] = x2 * c + x1 * sn;
    }
    for (int idx = tid; idx < NKV * HD; idx += 256) {
        int h = idx >> 7, d = idx & 127;
        g_v[((size_t)h * S_LEN + s) * HD + d] = row[NQ * HD + NKV * HD + h * HD + d];
    }
}

/* ---------------- flash attention: Br=64, Bc=64, causal ------------------ */
__global__ __launch_bounds__(256) void attn_kernel(const int* __restrict__ positions) {
    extern __shared__ float smf[];
    float* Qs = smf;
    float* Ks = Qs + 64 * 128;
    float* Vs = Ks + 64 * 129;
    float* Ps = Vs + 64 * 128;

    const int h  = blockIdx.y;
    const int qt = blockIdx.x;
    const int g  = h / GRP;
    const int tid = threadIdx.x;
    const int tx  = tid & 15;
    const int ty  = tid >> 4;
    const int r0  = ty * 4;

    const float* qbase = g_q + ((size_t)h * S_LEN + (size_t)qt * 64) * HD;
    for (int i = tid; i < 64 * 128 / 4; i += 256)
        ((float4*)Qs)[i] = ((const float4*)qbase)[i];

    float m_i[4], l_i[4], acc[4][8];
#pragma unroll
    for (int i = 0; i < 4; i++) {
        m_i[i] = -1e30f; l_i[i] = 0.0f;
#pragma unroll
        for (int j = 0; j < 8; j++) acc[i][j] = 0.0f;
    }
    int qpos[4];
#pragma unroll
    for (int i = 0; i < 4; i++) qpos[i] = positions[qt * 64 + r0 + i];

    for (int kt = 0; kt <= qt; kt++) {
        __syncthreads();
        const float* kbase = g_k + ((size_t)g * S_LEN + (size_t)kt * 64) * HD;
        const float* vbase = g_v + ((size_t)g * S_LEN + (size_t)kt * 64) * HD;
        for (int idx = tid; idx < 64 * 128; idx += 256) {
            int rr = idx >> 7, d = idx & 127;
            Ks[rr * 129 + d] = kbase[idx];
        }
        for (int i = tid; i < 64 * 128 / 4; i += 256)
            ((float4*)Vs)[i] = ((const float4*)vbase)[i];
        __syncthreads();

        float sc[4][4];
#pragma unroll
        for (int i = 0; i < 4; i++)
#pragma unroll
            for (int j = 0; j < 4; j++) sc[i][j] = 0.0f;
#pragma unroll 4
        for (int d = 0; d < 128; d++) {
            float qv[4], kv[4];
#pragma unroll
            for (int i = 0; i < 4; i++) qv[i] = Qs[(r0 + i) * 128 + d];
#pragma unroll
            for (int j = 0; j < 4; j++) kv[j] = Ks[(tx + 16 * j) * 129 + d];
#pragma unroll
            for (int i = 0; i < 4; i++)
#pragma unroll
                for (int j = 0; j < 4; j++) sc[i][j] += qv[i] * kv[j];
        }

        int kpos[4];
#pragma unroll
        for (int j = 0; j < 4; j++) kpos[j] = positions[kt * 64 + tx + 16 * j];
#pragma unroll
        for (int i = 0; i < 4; i++)
#pragma unroll
            for (int j = 0; j < 4; j++) {
                float v = sc[i][j] * ATT_SCALE;
                sc[i][j] = (qpos[i] >= kpos[j]) ? v : -1e30f;
            }

        float mt[4];
#pragma unroll
        for (int i = 0; i < 4; i++)
            mt[i] = fmaxf(fmaxf(sc[i][0], sc[i][1]), fmaxf(sc[i][2], sc[i][3]));
#pragma unroll
        for (int off = 8; off >= 1; off >>= 1)
#pragma unroll
            for (int i = 0; i < 4; i++)
                mt[i] = fmaxf(mt[i], __shfl_xor_sync(0xffffffffu, mt[i], off));

        float alpha[4], rs[4];
#pragma unroll
        for (int i = 0; i < 4; i++) {
            float mnew = fmaxf(m_i[i], mt[i]);
            alpha[i] = __expf(m_i[i] - mnew);
            m_i[i] = mnew;
            float s4 = 0.0f;
#pragma unroll
            for (int j = 0; j < 4; j++) {
                float p = __expf(sc[i][j] - mnew);
                sc[i][j] = p;
                s4 += p;
            }
            rs[i] = s4;
        }
#pragma unroll
        for (int off = 8; off >= 1; off >>= 1)
#pragma unroll
            for (int i = 0; i < 4; i++)
                rs[i] += __shfl_xor_sync(0xffffffffu, rs[i], off);
#pragma unroll
        for (int i = 0; i < 4; i++) {
            l_i[i] = l_i[i] * alpha[i] + rs[i];
#pragma unroll
            for (int jj = 0; jj < 8; jj++) acc[i][jj] *= alpha[i];
        }

#pragma unroll
        for (int i = 0; i < 4; i++)
#pragma unroll
            for (int j = 0; j < 4; j++)
                Ps[(r0 + i) * 65 + tx + 16 * j] = sc[i][j];
        __syncthreads();

#pragma unroll 4
        for (int c = 0; c < 64; c++) {
            float pv[4], vv[8];
#pragma unroll
            for (int i = 0; i < 4; i++) pv[i] = Ps[(r0 + i) * 65 + c];
#pragma unroll
            for (int jj = 0; jj < 8; jj++) vv[jj] = Vs[c * 128 + tx + 16 * jj];
#pragma unroll
            for (int i = 0; i < 4; i++)
#pragma unroll
                for (int jj = 0; jj < 8; jj++) acc[i][jj] += pv[i] * vv[jj];
        }
    }

#pragma unroll
    for (int i = 0; i < 4; i++) {
        float inv = 1.0f / l_i[i];
#pragma unroll
        for (int jj = 0; jj < 8; jj++)
            g_attn[(size_t)(qt * 64 + r0 + i) * (NQ * HD) + h * HD + tx + 16 * jj] =
                acc[i][jj] * inv;
    }
}

/* ------------------------------- launch ---------------------------------- */
extern "C" void kernel_launch(void* const* d_in, const int* in_sizes, int n_in,
                              void* d_out, int out_size) {
    const int*   positions = (const int*)  d_in[0];
    const float* hidden    = (const float*)d_in[1];
    const float* w_qkv     = (const float*)d_in[2];
    const float* w_o       = (const float*)d_in[3];
    float*       out       = (float*)d_out;
    (void)in_sizes; (void)n_in; (void)out_size;

    void *p_qkv = nullptr, *p_attn = nullptr, *p_abf = nullptr,
         *p_wq = nullptr, *p_wo = nullptr;
    cudaGetSymbolAddress(&p_qkv,  g_qkv);
    cudaGetSymbolAddress(&p_attn, g_attn);
    cudaGetSymbolAddress(&p_abf,  g_Abf);
    cudaGetSymbolAddress(&p_wq,   g_Wq);
    cudaGetSymbolAddress(&p_wo,   g_Wo);

    const int gemm_smem = 4 * TILE_BYTES;   /* 64 KB */
    cudaFuncSetAttribute(gemm_mma, cudaFuncAttributeMaxDynamicSharedMemorySize,
                         gemm_smem);

    /* 0) split-bf16 conversions */
    split_rows<<<(S_LEN * HID) / 256, 256>>>(hidden, (__nv_bfloat16*)p_abf);
    split_wt<<<dim3(HID / 32, QKV_N / 32), dim3(32, 8)>>>(w_qkv, (__nv_bfloat16*)p_wq, QKV_N);
    split_wt<<<dim3(HID / 32, HID / 32), dim3(32, 8)>>>(w_o, (__nv_bfloat16*)p_wo, HID);

    /* 1) QKV projection on tensor cores (mma.sync) */
    gemm_mma<<<dim3(S_LEN / 128, QKV_N / 128), 256, gemm_smem>>>(
        (const __nv_bfloat16*)p_abf, (const __nv_bfloat16*)p_wq, (float*)p_qkv, QKV_N);

    /* 2) RoPE + split */
    rope_split<<<S_LEN, 256>>>(positions);

    /* 3) causal flash attention (SIMT this round) */
    const int smem_bytes = (64 * 128 + 64 * 129 + 64 * 128 + 64 * 65) * 4;
    cudaFuncSetAttribute(attn_kernel, cudaFuncAttributeMaxDynamicSharedMemorySize,
                         smem_bytes);
    attn_kernel<<<dim3(S_LEN / 64, NQ), 256, smem_bytes>>>(positions);

    /* 4) output projection on tensor cores */
    split_rows<<<(S_LEN * HID) / 256, 256>>>((const float*)p_attn, (__nv_bfloat16*)p_abf);
    gemm_mma<<<dim3(S_LEN / 128, HID / 128), 256, gemm_smem>>>(
        (const __nv_bfloat16*)p_abf, (const __nv_bfloat16*)p_wo, out, HID);
}

// round 8
// speedup vs baseline: 2.2721x; 1.4476x over previous
#include <cuda_runtime.h>
#include <cuda_bf16.h>
#include <cstdint>
#include <cstddef>

#define S_LEN 4096
#define HID   4096
#define NQ    32
#define NKV   8
#define HD    128
#define HALF  64
#define GRP   4
#define QKV_N (NQ*HD + 2*NKV*HD)   /* 6144 */
#define ATT_SCALE 0.08838834764831845f
#define KP    (3*HID)              /* 12288 split-bf16 K */
#define KTILE 64
#define KITER (KP/KTILE)           /* 192 */

/* ---------------- scratch (device globals: allocation-free) -------------- */
__device__ float g_qkv [(size_t)S_LEN * QKV_N];
__device__ float g_attn[(size_t)S_LEN * NQ * HD];
__device__ __nv_bfloat16 g_qb [(size_t)NQ  * S_LEN * HD];  /* roped Q bf16 */
__device__ __nv_bfloat16 g_kb [(size_t)NKV * S_LEN * HD];  /* roped K bf16 */
__device__ __nv_bfloat16 g_Abf [(size_t)S_LEN * KP];
__device__ __nv_bfloat16 g_Wq  [(size_t)QKV_N * KP];
__device__ __nv_bfloat16 g_Wo  [(size_t)HID   * KP];

/* ======================= small asm helpers =============================== */
__device__ __forceinline__ uint32_t smem_u32(const void* p) {
    uint32_t a;
    asm("{ .reg .u64 t; cvta.to.shared.u64 t, %1; cvt.u32.u64 %0, t; }"
        : "=r"(a) : "l"(p));
    return a;
}
__device__ __forceinline__ uint32_t sw128(uint32_t off) {   /* Swizzle<3,4,3> */
    return off ^ ((off >> 3) & 0x70);
}
__device__ __forceinline__ void cp_async16(uint32_t saddr, const void* gaddr) {
    asm volatile("cp.async.cg.shared.global [%0], [%1], 16;"
                 :: "r"(saddr), "l"(gaddr));
}
#define CP_COMMIT() asm volatile("cp.async.commit_group;" ::: "memory")
#define CP_WAIT(n)  asm volatile("cp.async.wait_group %0;" :: "n"(n) : "memory")

__device__ __forceinline__ void ldsm_x4(uint32_t* f, uint32_t addr) {
    asm volatile("ldmatrix.sync.aligned.m8n8.x4.shared.b16 {%0,%1,%2,%3}, [%4];"
                 : "=r"(f[0]), "=r"(f[1]), "=r"(f[2]), "=r"(f[3]) : "r"(addr));
}
__device__ __forceinline__ void mma16816(float* d, const uint32_t* a,
                                         uint32_t b0, uint32_t b1) {
    asm volatile("mma.sync.aligned.m16n8k16.row.col.f32.bf16.bf16.f32 "
                 "{%0,%1,%2,%3}, {%4,%5,%6,%7}, {%8,%9}, {%0,%1,%2,%3};"
                 : "+f"(d[0]), "+f"(d[1]), "+f"(d[2]), "+f"(d[3])
                 : "r"(a[0]), "r"(a[1]), "r"(a[2]), "r"(a[3]), "r"(b0), "r"(b1));
}
__device__ __forceinline__ uint32_t pack_bf2(float x, float y) {
    __nv_bfloat162 h = __floats2bfloat162_rn(x, y);
    return *(uint32_t*)&h;
}

/* ================= split-bf16 conversion kernels ========================= */
__global__ __launch_bounds__(256) void split_rows(const float* __restrict__ src,
                                                  __nv_bfloat16* __restrict__ dst) {
    size_t idx = (size_t)blockIdx.x * 256 + threadIdx.x;
    int r = (int)(idx >> 12), k = (int)(idx & 4095);
    float x = src[idx];
    __nv_bfloat16 hi = __float2bfloat16_rn(x);
    __nv_bfloat16 lo = __float2bfloat16_rn(x - __bfloat162float(hi));
    size_t base = (size_t)r * KP + k;
    dst[base]          = hi;
    dst[base + HID]    = hi;
    dst[base + 2*HID]  = lo;
}
__global__ __launch_bounds__(256) void split_wt(const float* __restrict__ src,
                                                __nv_bfloat16* __restrict__ dst, int N) {
    __shared__ float t[32][33];
    int kb = blockIdx.x * 32, nb = blockIdx.y * 32;
    int tx = threadIdx.x, ty = threadIdx.y;
#pragma unroll
    for (int i = 0; i < 32; i += 8)
        t[ty + i][tx] = src[(size_t)(kb + ty + i) * N + nb + tx];
    __syncthreads();
#pragma unroll
    for (int i = 0; i < 32; i += 8) {
        int n = nb + ty + i, k = kb + tx;
        float x = t[tx][ty + i];
        __nv_bfloat16 hi = __float2bfloat16_rn(x);
        __nv_bfloat16 lo = __float2bfloat16_rn(x - __bfloat162float(hi));
        size_t base = (size_t)n * KP + k;
        dst[base]         = hi;
        dst[base + HID]   = lo;
        dst[base + 2*HID] = hi;
    }
}

/* ========== mma.sync bf16 GEMM (validated R7) ============================ */
#define TILE_BYTES 16384

__global__ __launch_bounds__(256) void gemm_mma(const __nv_bfloat16* __restrict__ A,
                                                const __nv_bfloat16* __restrict__ B,
                                                float* __restrict__ C, int N) {
    extern __shared__ char smc[];
    const uint32_t smb = smem_u32(smc);
    const int tid  = threadIdx.x;
    const int lane = tid & 31;
    const int wid  = tid >> 5;
    const int wm   = wid & 1;
    const int wn   = wid >> 1;
    const int m0   = blockIdx.x * 128;
    const int n0   = blockIdx.y * 128;

    const uint32_t sA[2] = { smb,              smb + 2*TILE_BYTES };
    const uint32_t sB[2] = { smb + TILE_BYTES, smb + 3*TILE_BYTES };

    const int r    = tid >> 1;
    const int halfc= tid & 1;
    const __nv_bfloat16* gA = A + (size_t)(m0 + r) * KP + halfc * 32;
    const __nv_bfloat16* gB = B + (size_t)(n0 + r) * KP + halfc * 32;
    const uint32_t soff[4] = {
        sw128((uint32_t)r * 128u + (uint32_t)(halfc * 4 + 0) * 16u),
        sw128((uint32_t)r * 128u + (uint32_t)(halfc * 4 + 1) * 16u),
        sw128((uint32_t)r * 128u + (uint32_t)(halfc * 4 + 2) * 16u),
        sw128((uint32_t)r * 128u + (uint32_t)(halfc * 4 + 3) * 16u) };

    float acc[4][4][4];
#pragma unroll
    for (int i = 0; i < 4; i++)
#pragma unroll
        for (int j = 0; j < 4; j++)
#pragma unroll
            for (int q = 0; q < 4; q++) acc[i][j][q] = 0.0f;

    const int arow = wm * 64 + (lane & 15);
    const int brow = wn * 32 + (lane & 15);
    const int kc   = lane >> 4;

#pragma unroll
    for (int p = 0; p < 2; p++) {
        const __nv_bfloat16* pa = gA + (size_t)p * KTILE;
        const __nv_bfloat16* pb = gB + (size_t)p * KTILE;
#pragma unroll
        for (int j = 0; j < 4; j++) {
            cp_async16(sA[p] + soff[j], pa + j * 8);
            cp_async16(sB[p] + soff[j], pb + j * 8);
        }
        CP_COMMIT();
    }

    for (int it = 0; it < KITER; ++it) {
        const int s = it & 1;
        if (it + 1 < KITER) CP_WAIT(1); else CP_WAIT(0);
        __syncthreads();

#pragma unroll
        for (int ks = 0; ks < 4; ks++) {
            uint32_t aF[4][4], bF[2][4];
            const uint32_t acol = (uint32_t)(ks * 2 + kc) * 16u;
#pragma unroll
            for (int mt = 0; mt < 4; mt++)
                ldsm_x4(aF[mt], sA[s] + sw128((uint32_t)(arow + mt * 16) * 128u + acol));
            ldsm_x4(bF[0], sB[s] + sw128((uint32_t)(brow)      * 128u + acol));
            ldsm_x4(bF[1], sB[s] + sw128((uint32_t)(brow + 16) * 128u + acol));
#pragma unroll
            for (int mt = 0; mt < 4; mt++)
#pragma unroll
                for (int nt = 0; nt < 4; nt++) {
                    const int gsel = nt >> 1, sub = nt & 1;
                    mma16816(acc[mt][nt], aF[mt], bF[gsel][sub], bF[gsel][sub + 2]);
                }
        }
        __syncthreads();

        if (it + 2 < KITER) {
            const int sn = s;
            const __nv_bfloat16* pa = gA + (size_t)(it + 2) * KTILE;
            const __nv_bfloat16* pb = gB + (size_t)(it + 2) * KTILE;
#pragma unroll
            for (int j = 0; j < 4; j++) {
                cp_async16(sA[sn] + soff[j], pa + j * 8);
                cp_async16(sB[sn] + soff[j], pb + j * 8);
            }
            CP_COMMIT();
        }
    }

#pragma unroll
    for (int mt = 0; mt < 4; mt++) {
        const int row0 = m0 + wm * 64 + mt * 16 + (lane >> 2);
#pragma unroll
        for (int nt = 0; nt < 4; nt++) {
            const int col = n0 + wn * 32 + nt * 8 + (lane & 3) * 2;
            float2 lo = { acc[mt][nt][0], acc[mt][nt][1] };
            float2 hi = { acc[mt][nt][2], acc[mt][nt][3] };
            *(float2*)(C + (size_t)row0 * N + col)       = lo;
            *(float2*)(C + (size_t)(row0 + 8) * N + col) = hi;
        }
    }
}

/* ---------------- RoPE -> bf16 per-head Q/K layouts ---------------------- */
__global__ __launch_bounds__(256) void rope_split(const int* __restrict__ positions) {
    const int s = blockIdx.x;
    const float* row = g_qkv + (size_t)s * QKV_N;
    const float pos = (float)positions[s];
    const int tid = threadIdx.x;
    const float LN_THETA_OVER_HALF = 9.210340371976184f / 64.0f;

    for (int idx = tid; idx < NQ * HALF; idx += 256) {
        int h = idx >> 6, j = idx & 63;
        float inv = expf(-(float)j * LN_THETA_OVER_HALF);
        float f = pos * inv;
        float c = cosf(f), sn = sinf(f);
        float x1 = row[h * HD + j];
        float x2 = row[h * HD + HALF + j];
        __nv_bfloat16* o = g_qb + ((size_t)h * S_LEN + s) * HD;
        o[j]        = __float2bfloat16_rn(x1 * c - x2 * sn);
        o[HALF + j] = __float2bfloat16_rn(x2 * c + x1 * sn);
    }
    for (int idx = tid; idx < NKV * HALF; idx += 256) {
        int h = idx >> 6, j = idx & 63;
        float inv = expf(-(float)j * LN_THETA_OVER_HALF);
        float f = pos * inv;
        float c = cosf(f), sn = sinf(f);
        const float* kr = row + NQ * HD;
        float x1 = kr[h * HD + j];
        float x2 = kr[h * HD + HALF + j];
        __nv_bfloat16* o = g_kb + ((size_t)h * S_LEN + s) * HD;
        o[j]        = __float2bfloat16_rn(x1 * c - x2 * sn);
        o[HALF + j] = __float2bfloat16_rn(x2 * c + x1 * sn);
    }
}

/* ======== tensor-core flash attention: Br=128, Bc=64, causal ============= */
/* smem: Qs 32KB | Ks 16KB | Vh 16KB | Vl 16KB | kpos 256B                   */
#define AS_Q   0
#define AS_K   32768
#define AS_VH  (AS_K + 16384)
#define AS_VL  (AS_VH + 16384)
#define AS_KP  (AS_VL + 16384)
#define AS_TOT (AS_KP + 256)

__global__ __launch_bounds__(256) void attn_mma(const int* __restrict__ positions) {
    extern __shared__ char smc[];
    const uint32_t smb = smem_u32(smc);
    int* kp = (int*)(smc + AS_KP);

    const int h  = blockIdx.y;
    const int qt = 31 - blockIdx.x;          /* long CTAs first */
    const int g  = h / GRP;
    const int tid  = threadIdx.x;
    const int lane = tid & 31;
    const int w    = tid >> 5;
    const int kc   = lane >> 4;

    /* ---- load Q tile (128 x 128 bf16), phys rows = m*2+half ---- */
    const __nv_bfloat16* qg = g_qb + ((size_t)h * S_LEN + (size_t)qt * 128) * HD;
    for (int c = tid; c < 2048; c += 256) {
        int s = c >> 4, cc = c & 15;
        uint32_t dst = smb + AS_Q +
            sw128((uint32_t)(s * 2 + (cc >> 3)) * 128u + (uint32_t)(cc & 7) * 16u);
        cp_async16(dst, (const char*)qg + (size_t)c * 16);
    }
    CP_COMMIT();

    const int qr = qt * 128 + w * 16 + (lane >> 2);
    const int qpos0 = positions[qr];
    const int qpos1 = positions[qr + 8];

    float m_i[2] = { -1e30f, -1e30f };
    float l_i[2] = { 0.0f, 0.0f };
    float acc[16][4];
#pragma unroll
    for (int t = 0; t < 16; t++)
#pragma unroll
        for (int q = 0; q < 4; q++) acc[t][q] = 0.0f;

    CP_WAIT(0);
    __syncthreads();

    const int ntiles = 2 * qt + 2;
    for (int kt = 0; kt < ntiles; kt++) {
        __syncthreads();   /* previous tile's smem consumers done */

        /* K tile (64 kv x 128 d bf16) -> phys [128 x 128B] */
        const __nv_bfloat16* kg = g_kb + ((size_t)g * S_LEN + (size_t)kt * 64) * HD;
        for (int c = tid; c < 1024; c += 256) {
            int s = c >> 4, cc = c & 15;
            uint32_t dst = smb + AS_K +
                sw128((uint32_t)(s * 2 + (cc >> 3)) * 128u + (uint32_t)(cc & 7) * 16u);
            cp_async16(dst, (const char*)kg + (size_t)c * 16);
        }
        CP_COMMIT();

        /* V tile: read fp32 from g_qkv, split hi/lo, store transposed [d][s] */
        {
            const float* vg = g_qkv + (size_t)(kt * 64) * QKV_N
                              + (NQ * HD + NKV * HD + g * HD);
            const int srow = tid >> 2;
            const int dq   = (tid & 3) * 32;
            const float4* vrow = (const float4*)(vg + (size_t)srow * QKV_N + dq);
#pragma unroll
            for (int q4 = 0; q4 < 8; q4++) {
                float4 v = vrow[q4];
                float e[4] = { v.x, v.y, v.z, v.w };
#pragma unroll
                for (int e4 = 0; e4 < 4; e4++) {
                    int d = dq + q4 * 4 + e4;
                    float x = e[e4];
                    __nv_bfloat16 hi = __float2bfloat16_rn(x);
                    __nv_bfloat16 lo = __float2bfloat16_rn(x - __bfloat162float(hi));
                    uint32_t off = sw128((uint32_t)d * 128u + (uint32_t)srow * 2u);
                    *(__nv_bfloat16*)(smc + AS_VH + off) = hi;
                    *(__nv_bfloat16*)(smc + AS_VL + off) = lo;
                }
            }
        }
        if (tid < 64) kp[tid] = positions[kt * 64 + tid];

        CP_WAIT(0);
        __syncthreads();

        /* ---- scores: S = Q K^T (16 x 64 per warp) ---- */
        float sc[8][4];
#pragma unroll
        for (int j = 0; j < 8; j++)
#pragma unroll
            for (int q = 0; q < 4; q++) sc[j][q] = 0.0f;

#pragma unroll
        for (int ks = 0; ks < 8; ks++) {
            const int cc = 2 * ks + kc;
            uint32_t aF[4];
            {
                int m = w * 16 + (lane & 15);
                ldsm_x4(aF, smb + AS_Q +
                    sw128((uint32_t)(m * 2 + (cc >> 3)) * 128u + (uint32_t)(cc & 7) * 16u));
            }
#pragma unroll
            for (int grp = 0; grp < 4; grp++) {
                uint32_t bF[4];
                int kv = grp * 16 + (lane & 15);
                ldsm_x4(bF, smb + AS_K +
                    sw128((uint32_t)(kv * 2 + (cc >> 3)) * 128u + (uint32_t)(cc & 7) * 16u));
                mma16816(sc[grp * 2 + 0], aF, bF[0], bF[2]);
                mma16816(sc[grp * 2 + 1], aF, bF[1], bF[3]);
            }
        }

        /* ---- scale + causal mask ---- */
#pragma unroll
        for (int j = 0; j < 8; j++) {
            int kcol = j * 8 + 2 * (lane & 3);
            int kp0 = kp[kcol], kp1 = kp[kcol + 1];
            float s0 = sc[j][0] * ATT_SCALE, s1 = sc[j][1] * ATT_SCALE;
            float s2 = sc[j][2] * ATT_SCALE, s3 = sc[j][3] * ATT_SCALE;
            sc[j][0] = (qpos0 >= kp0) ? s0 : -1e30f;
            sc[j][1] = (qpos0 >= kp1) ? s1 : -1e30f;
            sc[j][2] = (qpos1 >= kp0) ? s2 : -1e30f;
            sc[j][3] = (qpos1 >= kp1) ? s3 : -1e30f;
        }

        /* ---- online softmax ---- */
        float mt0 = -1e30f, mt1 = -1e30f;
#pragma unroll
        for (int j = 0; j < 8; j++) {
            mt0 = fmaxf(mt0, fmaxf(sc[j][0], sc[j][1]));
            mt1 = fmaxf(mt1, fmaxf(sc[j][2], sc[j][3]));
        }
        mt0 = fmaxf(mt0, __shfl_xor_sync(0xffffffffu, mt0, 1));
        mt0 = fmaxf(mt0, __shfl_xor_sync(0xffffffffu, mt0, 2));
        mt1 = fmaxf(mt1, __shfl_xor_sync(0xffffffffu, mt1, 1));
        mt1 = fmaxf(mt1, __shfl_xor_sync(0xffffffffu, mt1, 2));

        float mn0 = fmaxf(m_i[0], mt0), mn1 = fmaxf(m_i[1], mt1);
        float al0 = __expf(m_i[0] - mn0), al1 = __expf(m_i[1] - mn1);
        m_i[0] = mn0; m_i[1] = mn1;

        float rs0 = 0.0f, rs1 = 0.0f;
#pragma unroll
        for (int j = 0; j < 8; j++) {
            sc[j][0] = __expf(sc[j][0] - mn0);
            sc[j][1] = __expf(sc[j][1] - mn0);
            sc[j][2] = __expf(sc[j][2] - mn1);
            sc[j][3] = __expf(sc[j][3] - mn1);
            rs0 += sc[j][0] + sc[j][1];
            rs1 += sc[j][2] + sc[j][3];
        }
        rs0 += __shfl_xor_sync(0xffffffffu, rs0, 1);
        rs0 += __shfl_xor_sync(0xffffffffu, rs0, 2);
        rs1 += __shfl_xor_sync(0xffffffffu, rs1, 1);
        rs1 += __shfl_xor_sync(0xffffffffu, rs1, 2);
        l_i[0] = l_i[0] * al0 + rs0;
        l_i[1] = l_i[1] * al1 + rs1;

#pragma unroll
        for (int t = 0; t < 16; t++) {
            acc[t][0] *= al0; acc[t][1] *= al0;
            acc[t][2] *= al1; acc[t][3] *= al1;
        }

        /* ---- PV: acc += Phi*Vhi + Plo*Vhi + Phi*Vlo (K=64, 4 k16 steps) -- */
#pragma unroll
        for (int ks = 0; ks < 4; ks++) {
            const int j0 = 2 * ks, j1 = 2 * ks + 1;
            uint32_t ahi[4], alo[4];
            ahi[0] = pack_bf2(sc[j0][0], sc[j0][1]);
            ahi[1] = pack_bf2(sc[j0][2], sc[j0][3]);
            ahi[2] = pack_bf2(sc[j1][0], sc[j1][1]);
            ahi[3] = pack_bf2(sc[j1][2], sc[j1][3]);
            {
                __nv_bfloat162* hp;
                float l00, l01, l10, l11;
                hp = (__nv_bfloat162*)&ahi[0];
                l00 = sc[j0][0] - __bfloat162float(hp->x);
                l01 = sc[j0][1] - __bfloat162float(hp->y);
                alo[0] = pack_bf2(l00, l01);
                hp = (__nv_bfloat162*)&ahi[1];
                l10 = sc[j0][2] - __bfloat162float(hp->x);
                l11 = sc[j0][3] - __bfloat162float(hp->y);
                alo[1] = pack_bf2(l10, l11);
                hp = (__nv_bfloat162*)&ahi[2];
                l00 = sc[j1][0] - __bfloat162float(hp->x);
                l01 = sc[j1][1] - __bfloat162float(hp->y);
                alo[2] = pack_bf2(l00, l01);
                hp = (__nv_bfloat162*)&ahi[3];
                l10 = sc[j1][2] - __bfloat162float(hp->x);
                l11 = sc[j1][3] - __bfloat162float(hp->y);
                alo[3] = pack_bf2(l10, l11);
            }
            const uint32_t ccol = (uint32_t)(2 * ks + kc) * 16u;
#pragma unroll
            for (int grp = 0; grp < 8; grp++) {
                uint32_t vh[4], vl[4];
                uint32_t roff = sw128((uint32_t)(grp * 16 + (lane & 15)) * 128u + ccol);
                ldsm_x4(vh, smb + AS_VH + roff);
                ldsm_x4(vl, smb + AS_VL + roff);
                const int t0 = grp * 2, t1 = grp * 2 + 1;
                mma16816(acc[t0], ahi, vh[0], vh[2]);
                mma16816(acc[t1], ahi, vh[1], vh[3]);
                mma16816(acc[t0], alo, vh[0], vh[2]);
                mma16816(acc[t1], alo, vh[1], vh[3]);
                mma16816(acc[t0], ahi, vl[0], vl[2]);
                mma16816(acc[t1], ahi, vl[1], vl[3]);
            }
        }
    }

    /* ---- epilogue: normalize and write [s][h*D+d] fp32 ---- */
    float inv0 = 1.0f / l_i[0];
    float inv1 = 1.0f / l_i[1];
#pragma unroll
    for (int t = 0; t < 16; t++) {
        int col = h * HD + t * 8 + (lane & 3) * 2;
        float2 o0 = { acc[t][0] * inv0, acc[t][1] * inv0 };
        float2 o1 = { acc[t][2] * inv1, acc[t][3] * inv1 };
        *(float2*)(g_attn + (size_t)qr * (NQ * HD) + col)       = o0;
        *(float2*)(g_attn + (size_t)(qr + 8) * (NQ * HD) + col) = o1;
    }
}

/* ------------------------------- launch ---------------------------------- */
extern "C" void kernel_launch(void* const* d_in, const int* in_sizes, int n_in,
                              void* d_out, int out_size) {
    const int*   positions = (const int*)  d_in[0];
    const float* hidden    = (const float*)d_in[1];
    const float* w_qkv     = (const float*)d_in[2];
    const float* w_o       = (const float*)d_in[3];
    float*       out       = (float*)d_out;
    (void)in_sizes; (void)n_in; (void)out_size;

    void *p_qkv = nullptr, *p_attn = nullptr, *p_abf = nullptr,
         *p_wq = nullptr, *p_wo = nullptr;
    cudaGetSymbolAddress(&p_qkv,  g_qkv);
    cudaGetSymbolAddress(&p_attn, g_attn);
    cudaGetSymbolAddress(&p_abf,  g_Abf);
    cudaGetSymbolAddress(&p_wq,   g_Wq);
    cudaGetSymbolAddress(&p_wo,   g_Wo);

    const int gemm_smem = 4 * TILE_BYTES;   /* 64 KB */
    cudaFuncSetAttribute(gemm_mma, cudaFuncAttributeMaxDynamicSharedMemorySize,
                         gemm_smem);
    cudaFuncSetAttribute(attn_mma, cudaFuncAttributeMaxDynamicSharedMemorySize,
                         AS_TOT);

    /* 0) split-bf16 conversions */
    split_rows<<<(S_LEN * HID) / 256, 256>>>(hidden, (__nv_bfloat16*)p_abf);
    split_wt<<<dim3(HID / 32, QKV_N / 32), dim3(32, 8)>>>(w_qkv, (__nv_bfloat16*)p_wq, QKV_N);
    split_wt<<<dim3(HID / 32, HID / 32), dim3(32, 8)>>>(w_o, (__nv_bfloat16*)p_wo, HID);

    /* 1) QKV projection (tensor cores) */
    gemm_mma<<<dim3(S_LEN / 128, QKV_N / 128), 256, gemm_smem>>>(
        (const __nv_bfloat16*)p_abf, (const __nv_bfloat16*)p_wq, (float*)p_qkv, QKV_N);

    /* 2) RoPE -> bf16 Q/K */
    rope_split<<<S_LEN, 256>>>(positions);

    /* 3) tensor-core causal flash attention */
    attn_mma<<<dim3(32, NQ), 256, AS_TOT>>>(positions);

    /* 4) output projection (tensor cores) */
    split_rows<<<(S_LEN * HID) / 256, 256>>>((const float*)p_attn, (__nv_bfloat16*)p_abf);
    gemm_mma<<<dim3(S_LEN / 128, HID / 128), 256, gemm_smem>>>(
        (const __nv_bfloat16*)p_abf, (const __nv_bfloat16*)p_wo, out, HID);
}